// round 16
// baseline (speedup 1.0000x reference)
#include <cuda_runtime.h>
#include <cuda_bf16.h>
#include <cstdint>
#include <cstddef>

typedef unsigned long long ull;

#define BSZ   256
#define INK   2048
#define NCF   1000
#define ODEC  4096
#define NEG_SLOPE 0.1f

#define BK    32
#define NIT   (INK / BK)       // 64 iterations
#define STAGE_BYTES 49152      // Ah 8K @0, Al 8K @8192, Bh 16K @16384, Bl 16K @32768
#define SMEM_DYN (2 * STAGE_BYTES)
#define NTHR  512

// bf16 hi/lo scratch for x only (W1/fcW converted inline in mma_all)
__device__ __nv_bfloat16 g_xh[BSZ * INK];
__device__ __nv_bfloat16 g_xl[BSZ * INK];

// ---------------------------------------------------------------------------
__device__ __forceinline__ uint32_t smem_u32(const void* p) {
    return (uint32_t)__cvta_generic_to_shared(p);
}
__device__ __forceinline__ void cpasync16(uint32_t dst, const void* src) {
    asm volatile("cp.async.cg.shared.global [%0], [%1], 16;" :: "r"(dst), "l"(src));
}
__device__ __forceinline__ void cpcommit() {
    asm volatile("cp.async.commit_group;");
}
__device__ __forceinline__ void ldsm4(uint32_t& r0, uint32_t& r1, uint32_t& r2,
                                      uint32_t& r3, uint32_t addr) {
    asm volatile("ldmatrix.sync.aligned.m8n8.x4.shared.b16 {%0,%1,%2,%3}, [%4];"
                 : "=r"(r0), "=r"(r1), "=r"(r2), "=r"(r3) : "r"(addr));
}
__device__ __forceinline__ void mma16816(float* d, const uint32_t* a, const uint32_t* b) {
    asm volatile(
        "mma.sync.aligned.m16n8k16.row.col.f32.bf16.bf16.f32 "
        "{%0,%1,%2,%3}, {%4,%5,%6,%7}, {%8,%9}, {%0,%1,%2,%3};"
        : "+f"(d[0]), "+f"(d[1]), "+f"(d[2]), "+f"(d[3])
        : "r"(a[0]), "r"(a[1]), "r"(a[2]), "r"(a[3]), "r"(b[0]), "r"(b[1]));
}

__device__ __forceinline__ ull pk4(__nv_bfloat16 a, __nv_bfloat16 b,
                                   __nv_bfloat16 c, __nv_bfloat16 d) {
    return (ull)__bfloat16_as_ushort(a)
         | ((ull)__bfloat16_as_ushort(b) << 16)
         | ((ull)__bfloat16_as_ushort(c) << 32)
         | ((ull)__bfloat16_as_ushort(d) << 48);
}
__device__ __forceinline__ uint32_t pk2(__nv_bfloat16 a, __nv_bfloat16 b) {
    return (uint32_t)__bfloat16_as_ushort(a)
         | ((uint32_t)__bfloat16_as_ushort(b) << 16);
}
__device__ __forceinline__ void split1(float v, __nv_bfloat16& h, __nv_bfloat16& l) {
    h = __float2bfloat16_rn(v);
    l = __float2bfloat16_rn(v - __bfloat162float(h));
}

// ---------------------------------------------------------------------------
// x fp32 -> bf16 hi/lo (2 MB; ~free)
// ---------------------------------------------------------------------------
__global__ void conv_x_kernel(const float* __restrict__ x) {
    int t = blockIdx.x * blockDim.x + threadIdx.x;   // float4 idx, 131072 total
    float4 v = ((const float4*)x)[t];
    __nv_bfloat16 h0,h1,h2,h3,l0,l1,l2,l3;
    split1(v.x,h0,l0); split1(v.y,h1,l1); split1(v.z,h2,l2); split1(v.w,h3,l3);
    ((ull*)g_xh)[t] = pk4(h0,h1,h2,h3);
    ((ull*)g_xl)[t] = pk4(l0,l1,l2,l3);
}

// ---------------------------------------------------------------------------
// Fused mma kernel: CTA 128m x 256n, 16 warps of 32m x 64n (512 threads).
// B (W1 / fcW) loaded fp32 directly, split to bf16 h/l in registers, STS'd
// into swizzled smem tiles (register-staged double buffer).
// A (x) from precomputed bf16 via cp.async double buffer.
// Per ktile: (ah*bh) + (al*bh) with bh live, then (ah*bl).
// smem rows 64B (4 x 16B chunks), swizzle chunk ^ ((row>>1)&3).
// ---------------------------------------------------------------------------
__global__ __launch_bounds__(NTHR, 1)
void mma_all(const float* __restrict__ W1, const float* __restrict__ fcW,
             const float* __restrict__ b1, const float* __restrict__ W2,
             const float* __restrict__ b2, const float* __restrict__ fcb,
             float* __restrict__ out1, float* __restrict__ out2)
{
    extern __shared__ __align__(1024) char smbuf[];

    const int tid = threadIdx.x;
    const int lane = tid & 31;
    const int w = tid >> 5;
    const int warpm = w >> 2;       // 0..3  (32 m each)
    const int warpn = w & 3;        // 0..3  (64 n each)
    const bool is_fc = blockIdx.x >= 64;
    const int m0 = blockIdx.y * 128;
    const int n0 = (is_fc ? (blockIdx.x - 64) : blockIdx.x) * 256;
    const uint32_t sm_u = smem_u32(smbuf);

    float acc[2][8][4];
    #pragma unroll
    for (int mi = 0; mi < 2; mi++)
        #pragma unroll
        for (int ni = 0; ni < 8; ni++)
            #pragma unroll
            for (int q = 0; q < 4; q++) acc[mi][ni][q] = 0.f;

    // --- A cp.async: 1 chunk (16B) per thread per buffer ---
    const int ar = tid >> 2;                // 0..127
    const int ac = tid & 3;
    const uint32_t dstA = (uint32_t)(ar * 64 + ((ac ^ ((ar >> 1) & 3)) * 16));
    const size_t   srcA = (size_t)(m0 + ar) * INK + ac * 8;

    // --- B fp32 LDG mapping ---
    // decoder: thread owns decoder o_l, k-run kq*4 .. kq*4+3 (4 consecutive float4s,
    //          each float4 = W1[o][k][0..3] -> 4x4 register transpose h<->k)
    const int o_l = tid >> 3;               // 0..63
    const int kq  = tid & 7;                // k-chunk (4 k values)
    const float4* w1base = (const float4*)W1 + ((size_t)(n0 / 4 + o_l) * 2048 + kq * 4);
    // fc: thread owns rows fr+q*64, fixed k-chunk fc_c (k-contiguous float4)
    const int fr   = tid >> 3;              // 0..63 base row
    const int fc_c = tid & 7;

    auto ldgB = [&](float4* vB, int kt) {
        if (!is_fc) {
            const float4* p = w1base + (size_t)kt * BK;
            #pragma unroll
            for (int q = 0; q < 4; q++) vB[q] = __ldg(p + q);
        } else {
            #pragma unroll
            for (int q = 0; q < 4; q++) {
                const int row = fr + q * 64;
                if (n0 + row < NCF)
                    vB[q] = __ldg((const float4*)fcW + (size_t)(n0 + row) * 512 + kt * 8 + fc_c);
                else
                    vB[q] = make_float4(0.f, 0.f, 0.f, 0.f);
            }
        }
    };

    auto stsB = [&](int stage, const float4* vB) {
        char* base = smbuf + stage * STAGE_BYTES;
        if (!is_fc) {
            #pragma unroll
            for (int h = 0; h < 4; h++) {
                const int row = o_l * 4 + h;
                const int swz = (row >> 1) & 3;
                const uint32_t off = (uint32_t)(row * 64 + (((kq >> 1) ^ swz) * 16) + (kq & 1) * 8);
                float f0 = ((const float*)&vB[0])[h];
                float f1 = ((const float*)&vB[1])[h];
                float f2 = ((const float*)&vB[2])[h];
                float f3 = ((const float*)&vB[3])[h];
                __nv_bfloat16 h0,l0,h1,l1,h2,l2,h3,l3;
                split1(f0,h0,l0); split1(f1,h1,l1); split1(f2,h2,l2); split1(f3,h3,l3);
                *(ull*)(base + 16384 + off) = (ull)pk2(h0,h1) | ((ull)pk2(h2,h3) << 32);
                *(ull*)(base + 32768 + off) = (ull)pk2(l0,l1) | ((ull)pk2(l2,l3) << 32);
            }
        } else {
            #pragma unroll
            for (int q = 0; q < 4; q++) {
                const int row = fr + q * 64;
                const int swz = (row >> 1) & 3;
                const uint32_t off = (uint32_t)(row * 64 + (((fc_c >> 1) ^ swz) * 16) + (fc_c & 1) * 8);
                __nv_bfloat16 h0,l0,h1,l1,h2,l2,h3,l3;
                split1(vB[q].x,h0,l0); split1(vB[q].y,h1,l1);
                split1(vB[q].z,h2,l2); split1(vB[q].w,h3,l3);
                *(ull*)(base + 16384 + off) = (ull)pk2(h0,h1) | ((ull)pk2(h2,h3) << 32);
                *(ull*)(base + 32768 + off) = (ull)pk2(l0,l1) | ((ull)pk2(l2,l3) << 32);
            }
        }
    };

    auto cpA = [&](int stage, int kt) {
        const uint32_t base = sm_u + stage * STAGE_BYTES;
        const size_t koff = (size_t)kt * BK;
        cpasync16(base + dstA,        g_xh + srcA + koff);
        cpasync16(base + 8192 + dstA, g_xl + srcA + koff);
    };

    // --- ldmatrix lane addressing (64B rows) ---
    const int a_r  = (lane & 7) + ((lane >> 3) & 1) * 8;
    const int a_kh = (lane >> 4) & 1;
    uint32_t aRowOff[2]; int aXor[2];
    #pragma unroll
    for (int mi = 0; mi < 2; mi++) {
        const int m_r = warpm * 32 + mi * 16 + a_r;
        aRowOff[mi] = (uint32_t)(m_r * 64);
        aXor[mi] = (m_r >> 1) & 3;
    }
    const int b_r  = (lane & 7) + ((lane >> 4) & 1) * 8;
    const int b_kh = (lane >> 3) & 1;
    uint32_t bRowOff[4]; int bXor[4];
    #pragma unroll
    for (int bq = 0; bq < 4; bq++) {
        const int n_r = warpn * 64 + bq * 16 + b_r;
        bRowOff[bq] = (uint32_t)(16384 + n_r * 64);
        bXor[bq] = (n_r >> 1) & 3;
    }

    auto compute = [&](int stage) {
        const uint32_t base = sm_u + stage * STAGE_BYTES;
        #pragma unroll
        for (int ks = 0; ks < 2; ks++) {
            uint32_t ah[2][4], al[2][4], bb[4][4];
            #pragma unroll
            for (int mi = 0; mi < 2; mi++) {
                const uint32_t ch = (uint32_t)(((ks * 2 + a_kh) ^ aXor[mi]) << 4);
                ldsm4(ah[mi][0], ah[mi][1], ah[mi][2], ah[mi][3],
                      base + aRowOff[mi] + ch);
                ldsm4(al[mi][0], al[mi][1], al[mi][2], al[mi][3],
                      base + 8192 + aRowOff[mi] + ch);
            }
            #pragma unroll
            for (int bq = 0; bq < 4; bq++) {
                const uint32_t ch = (uint32_t)(((ks * 2 + b_kh) ^ bXor[bq]) << 4);
                ldsm4(bb[bq][0], bb[bq][1], bb[bq][2], bb[bq][3],
                      base + bRowOff[bq] + ch);
            }
            #pragma unroll
            for (int mi = 0; mi < 2; mi++)
                #pragma unroll
                for (int ni = 0; ni < 8; ni++)
                    mma16816(acc[mi][ni], ah[mi], &bb[ni >> 1][(ni & 1) * 2]);
            #pragma unroll
            for (int mi = 0; mi < 2; mi++)
                #pragma unroll
                for (int ni = 0; ni < 8; ni++)
                    mma16816(acc[mi][ni], al[mi], &bb[ni >> 1][(ni & 1) * 2]);
            // Bl (reuse bb registers)
            #pragma unroll
            for (int bq = 0; bq < 4; bq++) {
                const uint32_t ch = (uint32_t)(((ks * 2 + b_kh) ^ bXor[bq]) << 4);
                ldsm4(bb[bq][0], bb[bq][1], bb[bq][2], bb[bq][3],
                      base + 16384 + bRowOff[bq] + ch);
            }
            #pragma unroll
            for (int mi = 0; mi < 2; mi++)
                #pragma unroll
                for (int ni = 0; ni < 8; ni++)
                    mma16816(acc[mi][ni], ah[mi], &bb[ni >> 1][(ni & 1) * 2]);
        }
    };

    // --- pipeline: B reg-staged double buffer, A cp.async double buffer ---
    float4 vB[4];
    ldgB(vB, 0);
    cpA(0, 0); cpcommit();
    stsB(0, vB);
    ldgB(vB, 1);

    for (int it = 0; it < NIT; it++) {
        asm volatile("cp.async.wait_group 0;" ::: "memory");
        __syncthreads();
        if (it + 1 < NIT) {
            stsB((it + 1) & 1, vB);
            cpA((it + 1) & 1, it + 1); cpcommit();
        }
        if (it + 2 < NIT) ldgB(vB, it + 2);
        compute(it & 1);
    }

    // --- epilogue ---
    const int gid = lane >> 2;
    const int tq  = lane & 3;

    if (!is_fc) {
        #pragma unroll
        for (int ni = 0; ni < 8; ni++) {
            const int nb = n0 + warpn * 64 + ni * 8 + tq * 2;
            const float b1v0 = __ldg(&b1[nb]),     w2v0 = __ldg(&W2[nb]);
            const float b1v1 = __ldg(&b1[nb + 1]), w2v1 = __ldg(&W2[nb + 1]);
            const int dec = nb >> 2;
            const float b2v = __ldg(&b2[dec]);
            #pragma unroll
            for (int mi = 0; mi < 2; mi++) {
                #pragma unroll
                for (int h2 = 0; h2 < 2; h2++) {
                    const int gm = m0 + warpm * 32 + mi * 16 + gid + h2 * 8;
                    float v0 = acc[mi][ni][h2 * 2 + 0] + b1v0;
                    float v1 = acc[mi][ni][h2 * 2 + 1] + b1v1;
                    v0 = v0 >= 0.f ? v0 : NEG_SLOPE * v0;
                    v1 = v1 >= 0.f ? v1 : NEG_SLOPE * v1;
                    float p = v0 * w2v0 + v1 * w2v1;
                    p += __shfl_xor_sync(0xffffffffu, p, 1);
                    if ((lane & 1) == 0)
                        out2[(size_t)gm * ODEC + dec] = p + b2v;
                }
            }
        }
    } else {
        #pragma unroll
        for (int ni = 0; ni < 8; ni++) {
            const int nb = n0 + warpn * 64 + ni * 8 + tq * 2;
            float fb0 = 0.f, fb1 = 0.f;
            if (nb < NCF)     fb0 = __ldg(&fcb[nb]);
            if (nb + 1 < NCF) fb1 = __ldg(&fcb[nb + 1]);
            #pragma unroll
            for (int mi = 0; mi < 2; mi++) {
                #pragma unroll
                for (int h2 = 0; h2 < 2; h2++) {
                    const int gm = m0 + warpm * 32 + mi * 16 + gid + h2 * 8;
                    if (nb < NCF)
                        out1[(size_t)gm * NCF + nb]     = acc[mi][ni][h2 * 2 + 0] + fb0;
                    if (nb + 1 < NCF)
                        out1[(size_t)gm * NCF + nb + 1] = acc[mi][ni][h2 * 2 + 1] + fb1;
                }
            }
        }
    }
}

// ---------------------------------------------------------------------------
extern "C" void kernel_launch(void* const* d_in, const int* in_sizes, int n_in,
                              void* d_out, int out_size)
{
    const float* x   = (const float*)d_in[0];
    const float* fcW = (const float*)d_in[1];
    const float* fcb = (const float*)d_in[2];
    const float* W1  = (const float*)d_in[3];
    const float* b1  = (const float*)d_in[4];
    const float* W2  = (const float*)d_in[5];
    const float* b2  = (const float*)d_in[6];

    float* out1 = (float*)d_out;              // x1 [256,1000]
    float* out2 = out1 + BSZ * NCF;           // x2 [256,4096]

    cudaFuncSetAttribute(mma_all, cudaFuncAttributeMaxDynamicSharedMemorySize, SMEM_DYN);

    conv_x_kernel<<<512, 256>>>(x);
    mma_all<<<dim3(68, 2), NTHR, SMEM_DYN>>>(W1, fcW, b1, W2, b2, fcb, out1, out2);
}

// round 17
// speedup vs baseline: 1.0819x; 1.0819x over previous
#include <cuda_runtime.h>
#include <cuda_bf16.h>
#include <cstdint>
#include <cstddef>

typedef unsigned long long ull;

#define BSZ   256
#define INK   2048
#define NCF   1000
#define NCP   1024
#define ODEC  4096
#define NDEC  16384
#define NEG_SLOPE 0.1f

#define BK    32
#define NIT   (INK / BK)       // 64 iterations
#define STAGE_BYTES 32768      // Ah 8K @0, Al 8K @8192, Bh 8K @16384, Bl 8K @24576
#define NSTG  3
#define SMEM_DYN (NSTG * STAGE_BYTES)
#define NTHR  256

// bf16 hi/lo scratch
__device__ __nv_bfloat16 g_xh[BSZ * INK];
__device__ __nv_bfloat16 g_xl[BSZ * INK];
__device__ __nv_bfloat16 g_w1h[(size_t)NDEC * INK];
__device__ __nv_bfloat16 g_w1l[(size_t)NDEC * INK];
__device__ __nv_bfloat16 g_fwh[(size_t)NCP * INK];
__device__ __nv_bfloat16 g_fwl[(size_t)NCP * INK];

// ---------------------------------------------------------------------------
__device__ __forceinline__ uint32_t smem_u32(const void* p) {
    return (uint32_t)__cvta_generic_to_shared(p);
}
__device__ __forceinline__ void cpasync16(uint32_t dst, const void* src) {
    asm volatile("cp.async.cg.shared.global [%0], [%1], 16;" :: "r"(dst), "l"(src));
}
__device__ __forceinline__ void cpcommit() {
    asm volatile("cp.async.commit_group;");
}
__device__ __forceinline__ void ldsm4(uint32_t& r0, uint32_t& r1, uint32_t& r2,
                                      uint32_t& r3, uint32_t addr) {
    asm volatile("ldmatrix.sync.aligned.m8n8.x4.shared.b16 {%0,%1,%2,%3}, [%4];"
                 : "=r"(r0), "=r"(r1), "=r"(r2), "=r"(r3) : "r"(addr));
}
__device__ __forceinline__ void mma16816(float* d, const uint32_t* a, const uint32_t* b) {
    asm volatile(
        "mma.sync.aligned.m16n8k16.row.col.f32.bf16.bf16.f32 "
        "{%0,%1,%2,%3}, {%4,%5,%6,%7}, {%8,%9}, {%0,%1,%2,%3};"
        : "+f"(d[0]), "+f"(d[1]), "+f"(d[2]), "+f"(d[3])
        : "r"(a[0]), "r"(a[1]), "r"(a[2]), "r"(a[3]), "r"(b[0]), "r"(b[1]));
}

__device__ __forceinline__ ull pk4(__nv_bfloat16 a, __nv_bfloat16 b,
                                   __nv_bfloat16 c, __nv_bfloat16 d) {
    return (ull)__bfloat16_as_ushort(a)
         | ((ull)__bfloat16_as_ushort(b) << 16)
         | ((ull)__bfloat16_as_ushort(c) << 32)
         | ((ull)__bfloat16_as_ushort(d) << 48);
}
__device__ __forceinline__ uint32_t pk2(__nv_bfloat16 a, __nv_bfloat16 b) {
    return (uint32_t)__bfloat16_as_ushort(a)
         | ((uint32_t)__bfloat16_as_ushort(b) << 16);
}
__device__ __forceinline__ void split1(float v, __nv_bfloat16& h, __nv_bfloat16& l) {
    h = __float2bfloat16_rn(v);
    l = __float2bfloat16_rn(v - __bfloat162float(h));
}

// ---------------------------------------------------------------------------
// Merged conversion kernel (R15 version — near BW-bound)
// ---------------------------------------------------------------------------
__global__ __launch_bounds__(256)
void conv_all(const float* __restrict__ x, const float* __restrict__ W1,
              const float* __restrict__ fcW)
{
    __shared__ uint32_t sh_hi[4][1024];
    __shared__ uint32_t sh_lo[4][1024];

    const int bx = blockIdx.x;
    const int t = threadIdx.x;

    if (bx < 4096) {
        const int o = bx;
        const float4* src = (const float4*)(W1 + (size_t)o * 8192);
        #pragma unroll
        for (int q = 0; q < 4; q++) {
            const int j = t + q * 256;
            float4 v0 = src[2 * j];
            float4 v1 = src[2 * j + 1];
            float a0[4] = {v0.x, v0.y, v0.z, v0.w};
            float a1[4] = {v1.x, v1.y, v1.z, v1.w};
            #pragma unroll
            for (int h = 0; h < 4; h++) {
                __nv_bfloat16 h0, l0, h1, l1;
                split1(a0[h], h0, l0);
                split1(a1[h], h1, l1);
                sh_hi[h][j] = pk2(h0, h1);
                sh_lo[h][j] = pk2(l0, l1);
            }
        }
        __syncthreads();
        #pragma unroll
        for (int h = 0; h < 4; h++) {
            const size_t row = (size_t)(o * 4 + h) * INK;
            ((uint4*)(g_w1h + row))[t] = ((const uint4*)sh_hi[h])[t];
            ((uint4*)(g_w1l + row))[t] = ((const uint4*)sh_lo[h])[t];
        }
    } else if (bx < 4608) {
        const int g = (bx - 4096) * 256 + t;
        float4 v = ((const float4*)x)[g];
        __nv_bfloat16 h0,h1,h2,h3,l0,l1,l2,l3;
        split1(v.x,h0,l0); split1(v.y,h1,l1); split1(v.z,h2,l2); split1(v.w,h3,l3);
        ((ull*)g_xh)[g] = pk4(h0,h1,h2,h3);
        ((ull*)g_xl)[g] = pk4(l0,l1,l2,l3);
    } else {
        const int n = bx - 4608;
        const int base = t * 8;
        __nv_bfloat16 hb[8], lb[8];
        if (n < NCF) {
            const float4* src = (const float4*)(fcW + (size_t)n * INK + base);
            float4 a = src[0], b = src[1];
            float vv[8] = {a.x,a.y,a.z,a.w,b.x,b.y,b.z,b.w};
            #pragma unroll
            for (int j = 0; j < 8; j++) split1(vv[j], hb[j], lb[j]);
        } else {
            #pragma unroll
            for (int j = 0; j < 8; j++) { hb[j] = __float2bfloat16(0.f); lb[j] = __float2bfloat16(0.f); }
        }
        ull* dh = (ull*)(g_fwh + (size_t)n * INK + base);
        ull* dl = (ull*)(g_fwl + (size_t)n * INK + base);
        dh[0] = pk4(hb[0],hb[1],hb[2],hb[3]); dh[1] = pk4(hb[4],hb[5],hb[6],hb[7]);
        dl[0] = pk4(lb[0],lb[1],lb[2],lb[3]); dl[1] = pk4(lb[4],lb[5],lb[6],lb[7]);
    }
}

// ---------------------------------------------------------------------------
// Fused mma kernel: CTA 128m x 128n, 8 warps of 32m x 64n (256 threads),
// 2 CTAs/SM. BK=32, 3-stage pipeline, 64 iterations.
// All 3 products per ktile: (ah*bh) + (al*bh) with bh live, then (ah*bl).
// smem rows 64B (4 x 16B chunks), swizzle chunk ^ ((row>>1)&3).
// ---------------------------------------------------------------------------
__global__ __launch_bounds__(NTHR, 2)
void mma_all(const float* __restrict__ b1, const float* __restrict__ W2,
             const float* __restrict__ b2, const float* __restrict__ fcb,
             float* __restrict__ out1, float* __restrict__ out2)
{
    extern __shared__ __align__(1024) char smbuf[];

    const int tid = threadIdx.x;
    const int lane = tid & 31;
    const int w = tid >> 5;
    const int warpm = w >> 1;       // 0..3  (32 m each)
    const int warpn = w & 1;        // 0..1  (64 n each)
    const bool is_fc = blockIdx.x >= 128;
    const int m0 = blockIdx.y * 128;
    const int n0 = (is_fc ? (blockIdx.x - 128) : blockIdx.x) * 128;
    const uint32_t sm_u = smem_u32(smbuf);

    const __nv_bfloat16* Bh = is_fc ? g_fwh : g_w1h;
    const __nv_bfloat16* Bl = is_fc ? g_fwl : g_w1l;

    float acc[2][8][4];
    #pragma unroll
    for (int mi = 0; mi < 2; mi++)
        #pragma unroll
        for (int ni = 0; ni < 8; ni++)
            #pragma unroll
            for (int q = 0; q < 4; q++) acc[mi][ni][q] = 0.f;

    // --- cp.async slots: A 2 chunks/thread, B 2 chunks/thread (per h/l buffer) ---
    uint32_t dstA[2], dstB[2];
    size_t srcA[2], srcB[2];
    #pragma unroll
    for (int q = 0; q < 2; q++) {
        const int g = tid + q * NTHR;
        const int r = g >> 2, c = g & 3;
        const int cs = c ^ ((r >> 1) & 3);
        dstA[q] = (uint32_t)(r * 64 + cs * 16);
        srcA[q] = (size_t)(m0 + r) * INK + c * 8;
        dstB[q] = (uint32_t)(16384 + r * 64 + cs * 16);
        srcB[q] = (size_t)(n0 + r) * INK + c * 8;
    }

    auto do_load = [&](int stage, int kt) {
        const uint32_t base = sm_u + stage * STAGE_BYTES;
        const size_t koff = (size_t)kt * BK;
        #pragma unroll
        for (int q = 0; q < 2; q++) {
            cpasync16(base + dstA[q],        g_xh + srcA[q] + koff);
            cpasync16(base + 8192 + dstA[q], g_xl + srcA[q] + koff);
            cpasync16(base + dstB[q],        Bh + srcB[q] + koff);
            cpasync16(base + 8192 + dstB[q], Bl + srcB[q] + koff);
        }
    };

    // --- ldmatrix lane addressing (64B rows) ---
    const int a_r  = (lane & 7) + ((lane >> 3) & 1) * 8;
    const int a_kh = (lane >> 4) & 1;
    uint32_t aRowOff[2]; int aXor[2];
    #pragma unroll
    for (int mi = 0; mi < 2; mi++) {
        const int m_r = warpm * 32 + mi * 16 + a_r;
        aRowOff[mi] = (uint32_t)(m_r * 64);
        aXor[mi] = (m_r >> 1) & 3;
    }
    const int b_r  = (lane & 7) + ((lane >> 4) & 1) * 8;
    const int b_kh = (lane >> 3) & 1;
    uint32_t bRowOff[4]; int bXor[4];
    #pragma unroll
    for (int bq = 0; bq < 4; bq++) {
        const int n_r = warpn * 64 + bq * 16 + b_r;
        bRowOff[bq] = (uint32_t)(16384 + n_r * 64);
        bXor[bq] = (n_r >> 1) & 3;
    }

    auto compute = [&](int stage) {
        const uint32_t base = sm_u + stage * STAGE_BYTES;
        #pragma unroll
        for (int ks = 0; ks < 2; ks++) {
            uint32_t ah[2][4], al[2][4], bb[4][4];
            #pragma unroll
            for (int mi = 0; mi < 2; mi++) {
                const uint32_t ch = (uint32_t)(((ks * 2 + a_kh) ^ aXor[mi]) << 4);
                ldsm4(ah[mi][0], ah[mi][1], ah[mi][2], ah[mi][3],
                      base + aRowOff[mi] + ch);
                ldsm4(al[mi][0], al[mi][1], al[mi][2], al[mi][3],
                      base + 8192 + aRowOff[mi] + ch);
            }
            #pragma unroll
            for (int bq = 0; bq < 4; bq++) {
                const uint32_t ch = (uint32_t)(((ks * 2 + b_kh) ^ bXor[bq]) << 4);
                ldsm4(bb[bq][0], bb[bq][1], bb[bq][2], bb[bq][3],
                      base + bRowOff[bq] + ch);
            }
            #pragma unroll
            for (int mi = 0; mi < 2; mi++)
                #pragma unroll
                for (int ni = 0; ni < 8; ni++)
                    mma16816(acc[mi][ni], ah[mi], &bb[ni >> 1][(ni & 1) * 2]);
            #pragma unroll
            for (int mi = 0; mi < 2; mi++)
                #pragma unroll
                for (int ni = 0; ni < 8; ni++)
                    mma16816(acc[mi][ni], al[mi], &bb[ni >> 1][(ni & 1) * 2]);
            // Bl (reuse bb registers)
            #pragma unroll
            for (int bq = 0; bq < 4; bq++) {
                const uint32_t ch = (uint32_t)(((ks * 2 + b_kh) ^ bXor[bq]) << 4);
                ldsm4(bb[bq][0], bb[bq][1], bb[bq][2], bb[bq][3],
                      base + 8192 + bRowOff[bq] + ch);
            }
            #pragma unroll
            for (int mi = 0; mi < 2; mi++)
                #pragma unroll
                for (int ni = 0; ni < 8; ni++)
                    mma16816(acc[mi][ni], ah[mi], &bb[ni >> 1][(ni & 1) * 2]);
        }
    };

    // --- pipeline: 2 ahead, 3 stages ---
    do_load(0, 0); cpcommit();
    do_load(1, 1); cpcommit();

    int cs = 0;
    for (int it = 0; it < NIT; it++) {
        asm volatile("cp.async.wait_group 1;" ::: "memory");
        __syncthreads();
        if (it + 2 < NIT) {
            int ns = cs + 2; if (ns >= NSTG) ns -= NSTG;
            do_load(ns, it + 2);
        }
        cpcommit();
        compute(cs);
        if (++cs == NSTG) cs = 0;
    }

    // --- epilogue ---
    const int gid = lane >> 2;
    const int tq  = lane & 3;

    if (!is_fc) {
        #pragma unroll
        for (int ni = 0; ni < 8; ni++) {
            const int nb = n0 + warpn * 64 + ni * 8 + tq * 2;
            const float b1v0 = __ldg(&b1[nb]),     w2v0 = __ldg(&W2[nb]);
            const float b1v1 = __ldg(&b1[nb + 1]), w2v1 = __ldg(&W2[nb + 1]);
            const int dec = nb >> 2;
            const float b2v = __ldg(&b2[dec]);
            #pragma unroll
            for (int mi = 0; mi < 2; mi++) {
                #pragma unroll
                for (int h2 = 0; h2 < 2; h2++) {
                    const int gm = m0 + warpm * 32 + mi * 16 + gid + h2 * 8;
                    float v0 = acc[mi][ni][h2 * 2 + 0] + b1v0;
                    float v1 = acc[mi][ni][h2 * 2 + 1] + b1v1;
                    v0 = v0 >= 0.f ? v0 : NEG_SLOPE * v0;
                    v1 = v1 >= 0.f ? v1 : NEG_SLOPE * v1;
                    float p = v0 * w2v0 + v1 * w2v1;
                    p += __shfl_xor_sync(0xffffffffu, p, 1);
                    if ((lane & 1) == 0)
                        out2[(size_t)gm * ODEC + dec] = p + b2v;
                }
            }
        }
    } else {
        #pragma unroll
        for (int ni = 0; ni < 8; ni++) {
            const int nb = n0 + warpn * 64 + ni * 8 + tq * 2;
            float fb0 = 0.f, fb1 = 0.f;
            if (nb < NCF)     fb0 = __ldg(&fcb[nb]);
            if (nb + 1 < NCF) fb1 = __ldg(&fcb[nb + 1]);
            #pragma unroll
            for (int mi = 0; mi < 2; mi++) {
                #pragma unroll
                for (int h2 = 0; h2 < 2; h2++) {
                    const int gm = m0 + warpm * 32 + mi * 16 + gid + h2 * 8;
                    if (nb < NCF)
                        out1[(size_t)gm * NCF + nb]     = acc[mi][ni][h2 * 2 + 0] + fb0;
                    if (nb + 1 < NCF)
                        out1[(size_t)gm * NCF + nb + 1] = acc[mi][ni][h2 * 2 + 1] + fb1;
                }
            }
        }
    }
}

// ---------------------------------------------------------------------------
extern "C" void kernel_launch(void* const* d_in, const int* in_sizes, int n_in,
                              void* d_out, int out_size)
{
    const float* x   = (const float*)d_in[0];
    const float* fcW = (const float*)d_in[1];
    const float* fcb = (const float*)d_in[2];
    const float* W1  = (const float*)d_in[3];
    const float* b1  = (const float*)d_in[4];
    const float* W2  = (const float*)d_in[5];
    const float* b2  = (const float*)d_in[6];

    float* out1 = (float*)d_out;              // x1 [256,1000]
    float* out2 = out1 + BSZ * NCF;           // x2 [256,4096]

    cudaFuncSetAttribute(mma_all, cudaFuncAttributeMaxDynamicSharedMemorySize, SMEM_DYN);

    conv_all<<<5632, 256>>>(x, W1, fcW);
    mma_all<<<dim3(136, 2), NTHR, SMEM_DYN>>>(b1, W2, b2, fcb, out1, out2);
}